// round 2
// baseline (speedup 1.0000x reference)
#include <cuda_runtime.h>

// GaussianTrans: out = outX + outY
//   outX[b,r,c,d] = sum_h sigmoid(-(sh*(h-c)^2+bi) + attX[b,r,c,h]) * V[b,r,h,d]
//   outY[b,r,c,d] = sum_w sigmoid(-(sh*(w-r)^2+bi) + attY[b,c,r,w]) * V[b,w,c,d]
// B=16, H=W=64, D=512. Two launches of one templated GEMM-like kernel:
//   pass X: per (b, outer=r): A[m=c][k=h], V rows stride 512,   out rows stride 512,   write
//   pass Y: per (b, outer=c): A[m=r][k=w], V rows stride 32768, out rows stride 32768, accumulate
// Note V-offset and out-offset coincide in both passes.

#define TM 64
#define TN 128
#define TK 64

__device__ __forceinline__ unsigned long long pack2(float lo, float hi) {
    unsigned long long r;
    asm("mov.b64 %0, {%1, %2};" : "=l"(r) : "f"(lo), "f"(hi));
    return r;
}
__device__ __forceinline__ void unpack2(unsigned long long v, float& lo, float& hi) {
    asm("mov.b64 {%0, %1}, %2;" : "=f"(lo), "=f"(hi) : "l"(v));
}
// Packed fp32x2 FMA (Blackwell; ptxas will not auto-fuse — PTX only)
__device__ __forceinline__ unsigned long long fma2(unsigned long long a,
                                                   unsigned long long b,
                                                   unsigned long long c) {
    unsigned long long d;
    asm("fma.rn.f32x2 %0, %1, %2, %3;" : "=l"(d) : "l"(a), "l"(b), "l"(c));
    return d;
}

__device__ __forceinline__ float fast_sigmoid(float t) {
    // 1/(1+e^-t): MUFU.EX2 + MUFU.RCP path, rel err ~1e-6 — far inside 1e-3 budget
    return __fdividef(1.0f, 1.0f + __expf(-t));
}

template<bool PASSY>
__global__ __launch_bounds__(256, 3)
void gt_kernel(const float* __restrict__ att,
               const float* __restrict__ V,
               float* __restrict__ out,
               const float* __restrict__ shift,
               const float* __restrict__ bias)
{
    __shared__ float As[TM * TK];   // [m][k] post-sigmoid, 16 KB (layout == att layout)
    __shared__ float Vs[TK * TN];   // [k][n], 32 KB

    const int t     = threadIdx.x;
    const int dt    = blockIdx.x;   // 0..3 (d tile of 128)
    const int outer = blockIdx.y;   // r (pass X) or c (pass Y)
    const int b     = blockIdx.z;

    const float sh = shift[0];
    const float bi = bias[0];

    const int attBase = (b * 64 + outer) * 4096;
    const int off     = PASSY ? (b * 2097152 + outer * 512)
                              : ((b * 64 + outer) * 32768);
    const int vstride = PASSY ? 32768 : 512;
    const int dbase   = dt * TN;

    // --- A tile: sigmoid(dis + att), vectorized float4, contiguous & coalesced ---
    #pragma unroll
    for (int j = 0; j < 4; ++j) {
        const int idx4 = t + j * 256;          // 1024 float4 = 4096 elems
        const int m  = idx4 >> 4;
        const int k4 = (idx4 & 15) << 2;
        const float4 av = *reinterpret_cast<const float4*>(att + attBase + idx4 * 4);
        float d0 = (float)(k4 + 0 - m);
        float d1 = (float)(k4 + 1 - m);
        float d2 = (float)(k4 + 2 - m);
        float d3 = (float)(k4 + 3 - m);
        // -(sh*d^2 + bi) + a  ==  fmaf(-sh*d, d, a - bi)
        As[idx4 * 4 + 0] = fast_sigmoid(fmaf(-sh * d0, d0, av.x - bi));
        As[idx4 * 4 + 1] = fast_sigmoid(fmaf(-sh * d1, d1, av.y - bi));
        As[idx4 * 4 + 2] = fast_sigmoid(fmaf(-sh * d2, d2, av.z - bi));
        As[idx4 * 4 + 3] = fast_sigmoid(fmaf(-sh * d3, d3, av.w - bi));
    }

    // --- V tile: 64 rows x 128 floats; each warp does one 512B row segment ---
    #pragma unroll
    for (int j = 0; j < 8; ++j) {
        const int idx4 = t + j * 256;          // 2048 float4
        const int row  = idx4 >> 5;
        const int col  = (idx4 & 31) << 2;
        const float4 vv = *reinterpret_cast<const float4*>(
            V + off + row * vstride + dbase + col);
        *reinterpret_cast<float4*>(&Vs[row * TN + col]) = vv;
    }
    __syncthreads();

    const int tx = t & 15;
    const int ty = t >> 4;
    const int m0 = ty * 4;
    const int n0 = tx * 8;

    unsigned long long acc[4][4];   // [mi][n-pair], f32x2 packed along d
    #pragma unroll
    for (int i = 0; i < 4; ++i)
        #pragma unroll
        for (int j = 0; j < 4; ++j) acc[i][j] = 0ULL;

    #pragma unroll 8
    for (int k = 0; k < TK; ++k) {
        unsigned long long a2[4];
        #pragma unroll
        for (int i = 0; i < 4; ++i) {
            const float a = As[(m0 + i) * TK + k];   // broadcast-heavy LDS
            a2[i] = pack2(a, a);
        }
        const float4 v0 = *reinterpret_cast<const float4*>(&Vs[k * TN + n0]);
        const float4 v1 = *reinterpret_cast<const float4*>(&Vs[k * TN + n0 + 4]);
        unsigned long long vp[4];
        vp[0] = pack2(v0.x, v0.y);
        vp[1] = pack2(v0.z, v0.w);
        vp[2] = pack2(v1.x, v1.y);
        vp[3] = pack2(v1.z, v1.w);
        #pragma unroll
        for (int i = 0; i < 4; ++i)
            #pragma unroll
            for (int j = 0; j < 4; ++j)
                acc[i][j] = fma2(a2[i], vp[j], acc[i][j]);
    }

    // --- epilogue: pass X writes, pass Y read-modify-writes ---
    #pragma unroll
    for (int i = 0; i < 4; ++i) {
        float r[8];
        #pragma unroll
        for (int j = 0; j < 4; ++j) unpack2(acc[i][j], r[2 * j], r[2 * j + 1]);
        float* po = out + off + (m0 + i) * vstride + dbase + n0;
        if (PASSY) {
            const float4 o0 = *reinterpret_cast<const float4*>(po);
            const float4 o1 = *reinterpret_cast<const float4*>(po + 4);
            r[0] += o0.x; r[1] += o0.y; r[2] += o0.z; r[3] += o0.w;
            r[4] += o1.x; r[5] += o1.y; r[6] += o1.z; r[7] += o1.w;
        }
        *reinterpret_cast<float4*>(po)     = make_float4(r[0], r[1], r[2], r[3]);
        *reinterpret_cast<float4*>(po + 4) = make_float4(r[4], r[5], r[6], r[7]);
    }
}

extern "C" void kernel_launch(void* const* d_in, const int* in_sizes, int n_in,
                              void* d_out, int out_size) {
    (void)in_sizes; (void)n_in; (void)out_size;
    // metadata order: x(unused), attentionXFull, attentionYFull, valueFull, shift, bias
    const float* attX  = (const float*)d_in[1];
    const float* attY  = (const float*)d_in[2];
    const float* V     = (const float*)d_in[3];
    const float* shift = (const float*)d_in[4];
    const float* bias  = (const float*)d_in[5];
    float* out = (float*)d_out;

    dim3 grid(4, 64, 16);   // (d-tile, outer, b)
    dim3 block(256);
    gt_kernel<false><<<grid, block>>>(attX, V, out, shift, bias);  // outX: write
    gt_kernel<true ><<<grid, block>>>(attY, V, out, shift, bias);  // outY: accumulate
}

// round 3
// speedup vs baseline: 1.1049x; 1.1049x over previous
#include <cuda_runtime.h>

// GaussianTrans: out = outX + outY
//   outX[b,r,c,d] = sum_h sigmoid(-(sh*(h-c)^2+bi) + attX[b,r,c,h]) * V[b,r,h,d]
//   outY[b,r,c,d] = sum_w sigmoid(-(sh*(w-r)^2+bi) + attY[b,c,r,w]) * V[b,w,c,d]
// B=16, H=W=64, D=512.
// One templated 64x128x64 GEMM kernel, launched interleaved per 2 batches so
// pass Y's V reads and out RMW hit L2 (written/read by the matching pass X).

#define TM 64
#define TN 128
#define TK 64

__device__ __forceinline__ unsigned long long pack2(float lo, float hi) {
    unsigned long long r;
    asm("mov.b64 %0, {%1, %2};" : "=l"(r) : "f"(lo), "f"(hi));
    return r;
}
__device__ __forceinline__ void unpack2(unsigned long long v, float& lo, float& hi) {
    asm("mov.b64 {%0, %1}, %2;" : "=f"(lo), "=f"(hi) : "l"(v));
}
// Packed fp32x2 FMA (Blackwell, PTX-only; ptxas never auto-fuses)
__device__ __forceinline__ unsigned long long fma2(unsigned long long a,
                                                   unsigned long long b,
                                                   unsigned long long c) {
    unsigned long long d;
    asm("fma.rn.f32x2 %0, %1, %2, %3;" : "=l"(d) : "l"(a), "l"(b), "l"(c));
    return d;
}

__device__ __forceinline__ float fast_sigmoid(float t) {
    return __fdividef(1.0f, 1.0f + __expf(-t));
}

template<bool PASSY>
__global__ __launch_bounds__(128, 4)
void gt_kernel(const float* __restrict__ att,
               const float* __restrict__ V,
               float* __restrict__ out,
               const float* __restrict__ shift,
               const float* __restrict__ bias,
               int b0)
{
    __shared__ float As[TM * TK];   // [m][k] post-sigmoid, 16 KB
    __shared__ float Vs[TK * TN];   // [k][n], 32 KB

    const int t     = threadIdx.x;
    const int dt    = blockIdx.x;          // 0..3 (d tile of 128)
    const int outer = blockIdx.y;          // r (pass X) or c (pass Y)
    const int b     = b0 + blockIdx.z;     // 2 batches per launch

    const float sh = shift[0];
    const float bi = bias[0];

    const int attBase = (b * 64 + outer) * 4096;
    const int off     = PASSY ? (b * 2097152 + outer * 512)
                              : ((b * 64 + outer) * 32768);
    const int vstride = PASSY ? 32768 : 512;
    const int dbase   = dt * TN;

    // --- A tile: sigmoid(dis + att); float4 in, float4 out, fully coalesced ---
    #pragma unroll
    for (int j = 0; j < 8; ++j) {
        const int idx4 = t + j * 128;            // 1024 float4 = 4096 floats
        const int m  = idx4 >> 4;
        const int k4 = (idx4 & 15) << 2;
        const float4 av = *reinterpret_cast<const float4*>(att + attBase + idx4 * 4);
        float d0 = (float)(k4 + 0 - m);
        float d1 = (float)(k4 + 1 - m);
        float d2 = (float)(k4 + 2 - m);
        float d3 = (float)(k4 + 3 - m);
        float4 sv;
        sv.x = fast_sigmoid(fmaf(-sh * d0, d0, av.x - bi));
        sv.y = fast_sigmoid(fmaf(-sh * d1, d1, av.y - bi));
        sv.z = fast_sigmoid(fmaf(-sh * d2, d2, av.z - bi));
        sv.w = fast_sigmoid(fmaf(-sh * d3, d3, av.w - bi));
        *reinterpret_cast<float4*>(&As[idx4 * 4]) = sv;
    }

    // --- V tile: 64 rows x 128 floats ---
    #pragma unroll
    for (int j = 0; j < 16; ++j) {
        const int idx4 = t + j * 128;            // 2048 float4
        const int row  = idx4 >> 5;
        const int col  = (idx4 & 31) << 2;
        const float4 vv = *reinterpret_cast<const float4*>(
            V + off + row * vstride + dbase + col);
        *reinterpret_cast<float4*>(&Vs[row * TN + col]) = vv;
    }
    __syncthreads();

    // --- 8m x 8n microtile; n split into two 64-wide halves for
    //     conflict-free, lane-contiguous LDS.128 on V ---
    const int tx = t & 15;                  // n group
    const int ty = t >> 4;                  // m group (0..7)
    const int m0 = ty * 8;
    const int na = tx * 4;                  // n half A: [0,64)
    const int nb = 64 + tx * 4;             // n half B: [64,128)

    unsigned long long acc[8][4];           // [mi][2 pairs halfA, 2 pairs halfB]
    #pragma unroll
    for (int i = 0; i < 8; ++i)
        #pragma unroll
        for (int j = 0; j < 4; ++j) acc[i][j] = 0ULL;

    const float* Arow = As + m0 * TK;

    #pragma unroll 4
    for (int k = 0; k < TK; ++k) {
        // V: 2 x LDS.128, lanes contiguous within each 64-wide half
        const float4 v0 = *reinterpret_cast<const float4*>(&Vs[k * TN + na]);
        const float4 v1 = *reinterpret_cast<const float4*>(&Vs[k * TN + nb]);
        unsigned long long vp[4];
        vp[0] = pack2(v0.x, v0.y);
        vp[1] = pack2(v0.z, v0.w);
        vp[2] = pack2(v1.x, v1.y);
        vp[3] = pack2(v1.z, v1.w);
        // A: 8 broadcast scalars (<=2 distinct addresses per warp)
        #pragma unroll
        for (int i = 0; i < 8; ++i) {
            const float a = Arow[i * TK + k];
            const unsigned long long a2 = pack2(a, a);
            acc[i][0] = fma2(a2, vp[0], acc[i][0]);
            acc[i][1] = fma2(a2, vp[1], acc[i][1]);
            acc[i][2] = fma2(a2, vp[2], acc[i][2]);
            acc[i][3] = fma2(a2, vp[3], acc[i][3]);
        }
    }

    // --- epilogue: pass X writes; pass Y accumulates (out is L2-hot) ---
    #pragma unroll
    for (int i = 0; i < 8; ++i) {
        float r[8];
        #pragma unroll
        for (int j = 0; j < 4; ++j) unpack2(acc[i][j], r[2 * j], r[2 * j + 1]);
        float* po = out + off + (m0 + i) * vstride + dbase;
        if (PASSY) {
            const float4 o0 = *reinterpret_cast<const float4*>(po + na);
            const float4 o1 = *reinterpret_cast<const float4*>(po + nb);
            r[0] += o0.x; r[1] += o0.y; r[2] += o0.z; r[3] += o0.w;
            r[4] += o1.x; r[5] += o1.y; r[6] += o1.z; r[7] += o1.w;
        }
        *reinterpret_cast<float4*>(po + na) = make_float4(r[0], r[1], r[2], r[3]);
        *reinterpret_cast<float4*>(po + nb) = make_float4(r[4], r[5], r[6], r[7]);
    }
}

extern "C" void kernel_launch(void* const* d_in, const int* in_sizes, int n_in,
                              void* d_out, int out_size) {
    (void)in_sizes; (void)n_in; (void)out_size;
    // metadata order: x(unused), attentionXFull, attentionYFull, valueFull, shift, bias
    const float* attX  = (const float*)d_in[1];
    const float* attY  = (const float*)d_in[2];
    const float* V     = (const float*)d_in[3];
    const float* shift = (const float*)d_in[4];
    const float* bias  = (const float*)d_in[5];
    float* out = (float*)d_out;

    dim3 grid(4, 64, 2);   // (d-tile, outer, 2 batches)
    dim3 block(128);
    // Interleave per 2 batches: pass Y hits V[b] and outX[b] in L2.
    for (int b0 = 0; b0 < 16; b0 += 2) {
        gt_kernel<false><<<grid, block>>>(attX, V, out, shift, bias, b0);
        gt_kernel<true ><<<grid, block>>>(attY, V, out, shift, bias, b0);
    }
}

// round 4
// speedup vs baseline: 1.3736x; 1.2432x over previous
#include <cuda_runtime.h>

// GaussianTrans: out = outX + outY
//   outX[b,r,c,d] = sum_h sigmoid(-(sh*(h-c)^2+bi) + attX[b,r,c,h]) * V[b,r,h,d]
//   outY[b,r,c,d] = sum_w sigmoid(-(sh*(w-r)^2+bi) + attY[b,c,r,w]) * V[b,w,c,d]
// B=16, H=W=64, D=512.
// One templated 64x128x64 GEMM kernel; X/Y launches interleaved per 4 batches
// so pass Y's V reads and out RMW hit L2.

#define TM 64
#define TN 128
#define TK 64

__device__ __forceinline__ unsigned long long pack2(float lo, float hi) {
    unsigned long long r;
    asm("mov.b64 %0, {%1, %2};" : "=l"(r) : "f"(lo), "f"(hi));
    return r;
}
__device__ __forceinline__ void unpack2(unsigned long long v, float& lo, float& hi) {
    asm("mov.b64 {%0, %1}, %2;" : "=f"(lo), "=f"(hi) : "l"(v));
}
// Packed fp32x2 FMA (Blackwell, PTX-only; ptxas never auto-fuses)
__device__ __forceinline__ unsigned long long fma2(unsigned long long a,
                                                   unsigned long long b,
                                                   unsigned long long c) {
    unsigned long long d;
    asm("fma.rn.f32x2 %0, %1, %2, %3;" : "=l"(d) : "l"(a), "l"(b), "l"(c));
    return d;
}

__device__ __forceinline__ float fast_sigmoid(float t) {
    return __fdividef(1.0f, 1.0f + __expf(-t));
}

template<bool PASSY>
__global__ __launch_bounds__(128, 4)
void gt_kernel(const float* __restrict__ att,
               const float* __restrict__ V,
               float* __restrict__ out,
               const float* __restrict__ shift,
               const float* __restrict__ bias,
               int b0)
{
    __shared__ float As[TM * TK];   // [m][k] post-sigmoid, 16 KB
    __shared__ float Vs[TK * TN];   // [k][n], 32 KB

    const int t     = threadIdx.x;
    const int dt    = blockIdx.x;          // 0..3 (d tile of 128)
    const int outer = blockIdx.y;          // r (pass X) or c (pass Y)
    const int b     = b0 + blockIdx.z;     // 4 batches per launch

    const float sh = shift[0];
    const float bi = bias[0];

    const int attBase = (b * 64 + outer) * 4096;
    const int off     = PASSY ? (b * 2097152 + outer * 512)
                              : ((b * 64 + outer) * 32768);
    const int vstride = PASSY ? 32768 : 512;
    const int dbase   = dt * TN;

    // --- A tile: sigmoid(dis + att); float4 in/out, fully coalesced ---
    #pragma unroll
    for (int j = 0; j < 8; ++j) {
        const int idx4 = t + j * 128;            // 1024 float4 = 4096 floats
        const int m  = idx4 >> 4;
        const int k4 = (idx4 & 15) << 2;
        const float4 av = *reinterpret_cast<const float4*>(att + attBase + idx4 * 4);
        float d0 = (float)(k4 + 0 - m);
        float d1 = (float)(k4 + 1 - m);
        float d2 = (float)(k4 + 2 - m);
        float d3 = (float)(k4 + 3 - m);
        float4 sv;
        sv.x = fast_sigmoid(fmaf(-sh * d0, d0, av.x - bi));
        sv.y = fast_sigmoid(fmaf(-sh * d1, d1, av.y - bi));
        sv.z = fast_sigmoid(fmaf(-sh * d2, d2, av.z - bi));
        sv.w = fast_sigmoid(fmaf(-sh * d3, d3, av.w - bi));
        *reinterpret_cast<float4*>(&As[idx4 * 4]) = sv;
    }

    // --- V tile: 64 rows x 128 floats ---
    #pragma unroll
    for (int j = 0; j < 16; ++j) {
        const int idx4 = t + j * 128;            // 2048 float4
        const int row  = idx4 >> 5;
        const int col  = (idx4 & 31) << 2;
        const float4 vv = *reinterpret_cast<const float4*>(
            V + off + row * vstride + dbase + col);
        *reinterpret_cast<float4*>(&Vs[row * TN + col]) = vv;
    }
    __syncthreads();

    // --- 8m x 8n microtile; n split into two 64-wide halves so V LDS.128 is
    //     lane-contiguous / conflict-free; A loaded as LDS.64 over 2 k's
    //     (broadcast) to halve A wavefronts ---
    const int tx = t & 15;                  // n group
    const int ty = t >> 4;                  // m group (0..7)
    const int m0 = ty * 8;
    const int na = tx * 4;                  // n half A: [0,64)
    const int nb = 64 + tx * 4;             // n half B: [64,128)

    unsigned long long acc[8][4];
    #pragma unroll
    for (int i = 0; i < 8; ++i)
        #pragma unroll
        for (int j = 0; j < 4; ++j) acc[i][j] = 0ULL;

    #pragma unroll 2
    for (int kq = 0; kq < TK; kq += 2) {
        // A: 8 x LDS.64, <=2 distinct addresses per warp (broadcast)
        float2 a2k[8];
        #pragma unroll
        for (int i = 0; i < 8; ++i)
            a2k[i] = *reinterpret_cast<const float2*>(&As[(m0 + i) * TK + kq]);

        #pragma unroll
        for (int kk = 0; kk < 2; ++kk) {
            const int k = kq + kk;
            const float4 v0 = *reinterpret_cast<const float4*>(&Vs[k * TN + na]);
            const float4 v1 = *reinterpret_cast<const float4*>(&Vs[k * TN + nb]);
            unsigned long long vp0 = pack2(v0.x, v0.y);
            unsigned long long vp1 = pack2(v0.z, v0.w);
            unsigned long long vp2 = pack2(v1.x, v1.y);
            unsigned long long vp3 = pack2(v1.z, v1.w);
            #pragma unroll
            for (int i = 0; i < 8; ++i) {
                const float a = kk ? a2k[i].y : a2k[i].x;
                const unsigned long long a2 = pack2(a, a);
                acc[i][0] = fma2(a2, vp0, acc[i][0]);
                acc[i][1] = fma2(a2, vp1, acc[i][1]);
                acc[i][2] = fma2(a2, vp2, acc[i][2]);
                acc[i][3] = fma2(a2, vp3, acc[i][3]);
            }
        }
    }

    // --- epilogue: pass X writes; pass Y accumulates (out is L2-hot) ---
    #pragma unroll
    for (int i = 0; i < 8; ++i) {
        float r[8];
        #pragma unroll
        for (int j = 0; j < 4; ++j) unpack2(acc[i][j], r[2 * j], r[2 * j + 1]);
        float* po = out + off + (m0 + i) * vstride + dbase;
        if (PASSY) {
            const float4 o0 = *reinterpret_cast<const float4*>(po + na);
            const float4 o1 = *reinterpret_cast<const float4*>(po + nb);
            r[0] += o0.x; r[1] += o0.y; r[2] += o0.z; r[3] += o0.w;
            r[4] += o1.x; r[5] += o1.y; r[6] += o1.z; r[7] += o1.w;
        }
        *reinterpret_cast<float4*>(po + na) = make_float4(r[0], r[1], r[2], r[3]);
        *reinterpret_cast<float4*>(po + nb) = make_float4(r[4], r[5], r[6], r[7]);
    }
}

extern "C" void kernel_launch(void* const* d_in, const int* in_sizes, int n_in,
                              void* d_out, int out_size) {
    (void)in_sizes; (void)n_in; (void)out_size;
    // metadata order: x(unused), attentionXFull, attentionYFull, valueFull, shift, bias
    const float* attX  = (const float*)d_in[1];
    const float* attY  = (const float*)d_in[2];
    const float* V     = (const float*)d_in[3];
    const float* shift = (const float*)d_in[4];
    const float* bias  = (const float*)d_in[5];
    float* out = (float*)d_out;

    dim3 grid(4, 64, 4);   // (d-tile, outer, 4 batches)
    dim3 block(128);
    // Interleave per 4 batches: pass Y hits V[b] and outX[b] in L2.
    for (int b0 = 0; b0 < 16; b0 += 4) {
        gt_kernel<false><<<grid, block>>>(attX, V, out, shift, bias, b0);
        gt_kernel<true ><<<grid, block>>>(attY, V, out, shift, bias, b0);
    }
}

// round 6
// speedup vs baseline: 1.7337x; 1.2621x over previous
#include <cuda_runtime.h>
#include <cstdint>

// GaussianTrans via mma.sync tf32 (legacy HMMA path — arch-agnostic PTX,
// works with the harness's plain sm_103 ptxas target; tcgen05 is 'a'-gated).
//   outX[b,r,c,d] = sum_h sig(disX+attX) * V[b,r,h,d]   (pass X: write)
//   outY[b,r,c,d] = sum_w sig(disY+attY) * V[b,w,c,d]   (pass Y: accumulate)
// B=16, H=W=64, D=512. Per CTA: 64x128x64 GEMM tile. 4 warps, each 64m x 32n.
// X/Y launches interleaved per 4 batches so pass Y's V reads + out RMW hit L2.

#define SK 68    // As row stride (pad 4) -> conflict-free frag loads
#define SN 136   // Vs row stride (pad 8) -> conflict-free frag loads

static constexpr uint32_t SMEM_BYTES = (64 * SK + 64 * SN) * 4;  // 52224

static __device__ __forceinline__ uint32_t tf32rn(float f) {
    uint32_t r;
    asm("cvt.rn.tf32.f32 %0, %1;" : "=r"(r) : "f"(f));
    return r;
}
static __device__ __forceinline__ float fast_sigmoid(float t) {
    return __fdividef(1.0f, 1.0f + __expf(-t));
}
static __device__ __forceinline__ void mma_tf32(float& c0, float& c1, float& c2,
                                                float& c3, uint32_t a0, uint32_t a1,
                                                uint32_t a2, uint32_t a3,
                                                uint32_t b0, uint32_t b1) {
    asm volatile(
        "mma.sync.aligned.m16n8k8.row.col.f32.tf32.tf32.f32 "
        "{%0,%1,%2,%3}, {%4,%5,%6,%7}, {%8,%9}, {%0,%1,%2,%3};"
        : "+f"(c0), "+f"(c1), "+f"(c2), "+f"(c3)
        : "r"(a0), "r"(a1), "r"(a2), "r"(a3), "r"(b0), "r"(b1));
}

template<bool PASSY>
__global__ __launch_bounds__(128, 3)
void gt_mma(const float* __restrict__ att, const float* __restrict__ V,
            float* __restrict__ out, const float* __restrict__ shift,
            const float* __restrict__ bias, int b0)
{
    extern __shared__ float smem[];
    float* As = smem;             // [64][SK], tf32 bit patterns
    float* Vs = smem + 64 * SK;   // [64][SN], tf32 bit patterns

    const int tid = threadIdx.x;
    const int dt    = blockIdx.x;          // 0..3 (d tile of 128)
    const int outer = blockIdx.y;          // r (pass X) or c (pass Y)
    const int b     = b0 + blockIdx.z;     // 4 batches per launch

    const float sh = shift[0], bi = bias[0];
    const int attBase = (b * 64 + outer) * 4096;
    const int off     = PASSY ? (b * 2097152 + outer * 512)
                              : ((b * 64 + outer) * 32768);
    const int vstride = PASSY ? 32768 : 512;
    const int dbase   = dt * 128;

    // --- A tile: sigmoid(dis + att) -> tf32-RN; coalesced float4 in ---
    #pragma unroll
    for (int j = 0; j < 8; ++j) {
        const int idx4 = tid + j * 128;          // 1024 float4 = 4096 elems
        const int m  = idx4 >> 4;
        const int k4 = (idx4 & 15) << 2;
        const float4 av = *reinterpret_cast<const float4*>(att + attBase + idx4 * 4);
        float d0 = (float)(k4 + 0 - m);
        float d1 = (float)(k4 + 1 - m);
        float d2 = (float)(k4 + 2 - m);
        float d3 = (float)(k4 + 3 - m);
        uint4 sv;
        sv.x = tf32rn(fast_sigmoid(fmaf(-sh * d0, d0, av.x - bi)));
        sv.y = tf32rn(fast_sigmoid(fmaf(-sh * d1, d1, av.y - bi)));
        sv.z = tf32rn(fast_sigmoid(fmaf(-sh * d2, d2, av.z - bi)));
        sv.w = tf32rn(fast_sigmoid(fmaf(-sh * d3, d3, av.w - bi)));
        *reinterpret_cast<uint4*>(&As[m * SK + k4]) = sv;
    }

    // --- V tile: 64 k-rows x 128 d, tf32-RN ---
    #pragma unroll
    for (int j = 0; j < 16; ++j) {
        const int idx4 = tid + j * 128;          // 2048 float4
        const int row  = idx4 >> 5;
        const int col  = (idx4 & 31) << 2;
        const float4 vv = *reinterpret_cast<const float4*>(
            V + off + row * vstride + dbase + col);
        uint4 tv;
        tv.x = tf32rn(vv.x); tv.y = tf32rn(vv.y);
        tv.z = tf32rn(vv.z); tv.w = tf32rn(vv.w);
        *reinterpret_cast<uint4*>(&Vs[row * SN + col]) = tv;
    }
    __syncthreads();

    // --- mma.sync m16n8k8 tf32: warp = 64m x 32n (4 m-tiles x 4 n-tiles) ---
    const int wid  = tid >> 5;
    const int lane = tid & 31;
    const int grp  = lane >> 2;     // 0..7
    const int tig  = lane & 3;      // 0..3
    const int n0   = wid * 32;

    float acc[4][4][4];
    #pragma unroll
    for (int mt = 0; mt < 4; ++mt)
        #pragma unroll
        for (int nt = 0; nt < 4; ++nt)
            #pragma unroll
            for (int q = 0; q < 4; ++q) acc[mt][nt][q] = 0.0f;

    const uint32_t* Au = reinterpret_cast<const uint32_t*>(As);
    const uint32_t* Vu = reinterpret_cast<const uint32_t*>(Vs);

    #pragma unroll
    for (int k8 = 0; k8 < 8; ++k8) {
        const int kb = k8 * 8;
        uint32_t a[4][4];
        #pragma unroll
        for (int mt = 0; mt < 4; ++mt) {
            const int base = (mt * 16 + grp) * SK + kb + tig;
            a[mt][0] = Au[base];                 // (row,       col)
            a[mt][1] = Au[base + 8 * SK];        // (row+8,     col)
            a[mt][2] = Au[base + 4];             // (row,       col+4)
            a[mt][3] = Au[base + 8 * SK + 4];    // (row+8,     col+4)
        }
        #pragma unroll
        for (int nt = 0; nt < 4; ++nt) {
            const int nc = n0 + nt * 8 + grp;
            const uint32_t bq0 = Vu[(kb + tig) * SN + nc];
            const uint32_t bq1 = Vu[(kb + tig + 4) * SN + nc];
            #pragma unroll
            for (int mt = 0; mt < 4; ++mt)
                mma_tf32(acc[mt][nt][0], acc[mt][nt][1],
                         acc[mt][nt][2], acc[mt][nt][3],
                         a[mt][0], a[mt][1], a[mt][2], a[mt][3], bq0, bq1);
        }
    }

    // --- epilogue: c0,c1 -> (row, 2 cols); c2,c3 -> (row+8, 2 cols) ---
    #pragma unroll
    for (int mt = 0; mt < 4; ++mt) {
        #pragma unroll
        for (int nt = 0; nt < 4; ++nt) {
            const int col  = dbase + n0 + nt * 8 + tig * 2;
            const int row0 = mt * 16 + grp;
            float* p0 = out + off + row0 * vstride + col;
            float* p1 = p0 + 8 * vstride;
            float2 w0 = make_float2(acc[mt][nt][0], acc[mt][nt][1]);
            float2 w1 = make_float2(acc[mt][nt][2], acc[mt][nt][3]);
            if (PASSY) {
                const float2 o0 = *reinterpret_cast<const float2*>(p0);
                const float2 o1 = *reinterpret_cast<const float2*>(p1);
                w0.x += o0.x; w0.y += o0.y;
                w1.x += o1.x; w1.y += o1.y;
            }
            *reinterpret_cast<float2*>(p0) = w0;
            *reinterpret_cast<float2*>(p1) = w1;
        }
    }
}

extern "C" void kernel_launch(void* const* d_in, const int* in_sizes, int n_in,
                              void* d_out, int out_size) {
    (void)in_sizes; (void)n_in; (void)out_size;
    // metadata order: x(unused), attentionXFull, attentionYFull, valueFull, shift, bias
    const float* attX  = (const float*)d_in[1];
    const float* attY  = (const float*)d_in[2];
    const float* V     = (const float*)d_in[3];
    const float* shift = (const float*)d_in[4];
    const float* bias  = (const float*)d_in[5];
    float* out = (float*)d_out;

    cudaFuncSetAttribute(gt_mma<false>,
                         cudaFuncAttributeMaxDynamicSharedMemorySize, SMEM_BYTES);
    cudaFuncSetAttribute(gt_mma<true>,
                         cudaFuncAttributeMaxDynamicSharedMemorySize, SMEM_BYTES);

    dim3 grid(4, 64, 4);   // (d-tile, outer, 4 batches)
    dim3 block(128);
    // Interleave per 4 batches: pass Y hits V[b] and outX[b] in L2.
    for (int b0 = 0; b0 < 16; b0 += 4) {
        gt_mma<false><<<grid, block, SMEM_BYTES>>>(attX, V, out, shift, bias, b0);
        gt_mma<true ><<<grid, block, SMEM_BYTES>>>(attY, V, out, shift, bias, b0);
    }
}